// round 2
// baseline (speedup 1.0000x reference)
#include <cuda_runtime.h>
#include <math.h>

#define BATCH 2
#define SEQLEN 1024
#define T_TOK (BATCH*SEQLEN)     // 2048
#define DIN 768
#define DM 1536
#define DS 16
#define DD 96
#define KCONV 4
#define NLAYER 4
#define VOCAB 32000
#define EPSF 1e-6f

// ---------------- scratch (device globals: no allocation allowed) ----------------
__device__ float g_seq[T_TOK*DIN];
__device__ float g_xn[T_TOK*DIN];
__device__ float g_ab[T_TOK*2*DM];
__device__ float g_a[T_TOK*DM];
__device__ float g_bcd[T_TOK*128];      // cols 0-15 Bm, 16-31 Cm, 32-127 (a@sD0^T)
__device__ float g_delta[T_TOK*DM];
__device__ float g_y[T_TOK*DM];
__device__ float g_w128[NLAYER*128*DM]; // concat [sB;sC;sD0] per layer

// ---------------- elementwise helpers ----------------
__device__ __forceinline__ float siluf(float x) { return x / (1.f + __expf(-x)); }

// ---------------- embedding gather ----------------
__global__ void k_embed(const int* __restrict__ tok, const float* __restrict__ emb) {
    int i = blockIdx.x*blockDim.x + threadIdx.x;
    if (i >= T_TOK*DIN) return;
    int t = i / DIN, c = i % DIN;
    g_seq[i] = emb[(long)tok[t]*DIN + c];
}

// ---------------- rmsnorm: one block per token row ----------------
__global__ void k_rmsnorm(const float* __restrict__ x, const float* __restrict__ w,
                          float* __restrict__ out) {
    __shared__ float red[256];
    int t = blockIdx.x;
    const float* xr = x + (long)t*DIN;
    float s = 0.f;
    for (int c = threadIdx.x; c < DIN; c += 256) { float v = xr[c]; s += v*v; }
    red[threadIdx.x] = s; __syncthreads();
    for (int o = 128; o > 0; o >>= 1) {
        if (threadIdx.x < o) red[threadIdx.x] += red[threadIdx.x+o];
        __syncthreads();
    }
    float inv = rsqrtf(red[0] * (1.f/DIN) + EPSF);
    for (int c = threadIdx.x; c < DIN; c += 256) out[(long)t*DIN + c] = xr[c]*inv*w[c];
}

// ---------------- build concatenated [sB;sC;sD0] weight (all layers) ----------------
__global__ void k_build_w128(const float* __restrict__ sB, const float* __restrict__ sC,
                             const float* __restrict__ sD0) {
    int i = blockIdx.x*blockDim.x + threadIdx.x;
    if (i >= NLAYER*128*DM) return;
    int l = i / (128*DM);
    int r = (i / DM) % 128;
    int k = i % DM;
    float v;
    if (r < 16)       v = sB[((long)l*16 + r)*DM + k];
    else if (r < 32)  v = sC[((long)l*16 + (r-16))*DM + k];
    else              v = sD0[((long)l*96 + (r-32))*DM + k];
    g_w128[i] = v;
}

// ---------------- depthwise causal conv (K=4) + silu ----------------
__global__ void k_conv_silu(const float* __restrict__ cw, const float* __restrict__ cb) {
    int i = blockIdx.x*blockDim.x + threadIdx.x;
    if (i >= T_TOK*DM) return;
    int t = i / DM, d = i % DM;
    int l = t % SEQLEN;
    float acc = cb[d];
    #pragma unroll
    for (int j = 0; j < KCONV; j++) {
        int lj = l - (KCONV-1) + j;
        if (lj >= 0) acc += cw[d*KCONV + j] * g_ab[(long)(t - (KCONV-1) + j)*(2*DM) + d];
    }
    g_a[i] = siluf(acc);
}

// ---------------- SSM scan: 16 lanes (s) per (b,d) group; gate fused ----------------
__global__ void k_scan(const float* __restrict__ A_log, const float* __restrict__ Dp) {
    int tid = threadIdx.x;
    int g = blockIdx.x*16 + (tid >> 4);   // group over BATCH*DM
    int s = tid & 15;
    int b = g / DM, d = g % DM;
    float Ads = -__expf(A_log[d*DS + s]);
    float Dd  = Dp[d];
    float h = 0.f;
    int base = b * SEQLEN;
    for (int l = 0; l < SEQLEN; l++) {
        int t = base + l;
        float dv = g_delta[(long)t*DM + d];
        float av = g_a[(long)t*DM + d];
        float bm = g_bcd[(long)t*128 + s];
        float cm = g_bcd[(long)t*128 + 16 + s];
        float abar = __expf(dv * Ads);
        h = fmaf(abar, h, dv * bm * av);
        float y = h * cm;
        y += __shfl_xor_sync(0xffffffffu, y, 8);
        y += __shfl_xor_sync(0xffffffffu, y, 4);
        y += __shfl_xor_sync(0xffffffffu, y, 2);
        y += __shfl_xor_sync(0xffffffffu, y, 1);
        if (s == 0) {
            float bg = g_ab[(long)t*(2*DM) + DM + d];
            g_y[(long)t*DM + d] = (y + Dd*av) * siluf(bg);
        }
    }
}

// ---------------- SGEMM: C[M,N] (op)= A[M,K] @ W[N,K]^T ----------------
// 128x128 tile, BK=8, 256 threads, 8x8 micro-tile per thread.
// EPI: 0 = store, 1 = accumulate (residual), 2 = softplus(acc + bias[n])
template<int EPI>
__global__ void __launch_bounds__(256, 2)
k_sgemm(const float* __restrict__ A, const float* __restrict__ W,
        float* __restrict__ C, const float* __restrict__ bias,
        int M, int N, int K, int lda, int ldw, int ldc)
{
    __shared__ float As[8][128+4];
    __shared__ float Ws[8][128+4];
    int tid = threadIdx.x;
    int bm = blockIdx.y * 128;
    int bn = blockIdx.x * 128;
    int lm = tid >> 1;             // 0..127 row within tile
    int lk = (tid & 1) * 4;        // 0 or 4
    int ty = tid >> 4, tx = tid & 15;

    const float* Ap = A + (long)(bm + lm)*lda + lk;
    const float* Wp = W + (long)(bn + lm)*ldw + lk;

    float acc[8][8];
    #pragma unroll
    for (int i = 0; i < 8; i++)
        #pragma unroll
        for (int j = 0; j < 8; j++) acc[i][j] = 0.f;

    int nk = K >> 3;
    for (int kt = 0; kt < nk; kt++) {
        float4 av = *(const float4*)(Ap + kt*8);
        float4 wv = *(const float4*)(Wp + kt*8);
        __syncthreads();
        As[lk+0][lm] = av.x; As[lk+1][lm] = av.y; As[lk+2][lm] = av.z; As[lk+3][lm] = av.w;
        Ws[lk+0][lm] = wv.x; Ws[lk+1][lm] = wv.y; Ws[lk+2][lm] = wv.z; Ws[lk+3][lm] = wv.w;
        __syncthreads();
        #pragma unroll
        for (int kk = 0; kk < 8; kk++) {
            float ar[8], wr[8];
            #pragma unroll
            for (int i = 0; i < 8; i++) ar[i] = As[kk][ty*8 + i];
            #pragma unroll
            for (int j = 0; j < 8; j++) wr[j] = Ws[kk][tx*8 + j];
            #pragma unroll
            for (int i = 0; i < 8; i++)
                #pragma unroll
                for (int j = 0; j < 8; j++)
                    acc[i][j] = fmaf(ar[i], wr[j], acc[i][j]);
        }
    }

    #pragma unroll
    for (int i = 0; i < 8; i++) {
        int m = bm + ty*8 + i;
        #pragma unroll
        for (int j = 0; j < 8; j++) {
            int n = bn + tx*8 + j;
            float v = acc[i][j];
            float* cp = &C[(long)m*ldc + n];
            if (EPI == 0) {
                *cp = v;
            } else if (EPI == 1) {
                *cp += v;
            } else {
                v += bias[n];
                *cp = (v > 20.f) ? v : log1pf(__expf(v));
            }
        }
    }
}

// ---------------- host launcher ----------------
extern "C" void kernel_launch(void* const* d_in, const int* in_sizes, int n_in,
                              void* d_out, int out_size) {
    const int*   tok      = (const int*)  d_in[0];
    const float* emb      = (const float*)d_in[1];
    const float* in_proj  = (const float*)d_in[2];
    const float* out_proj = (const float*)d_in[3];
    const float* sB       = (const float*)d_in[4];
    const float* sC       = (const float*)d_in[5];
    const float* sD0      = (const float*)d_in[6];
    const float* sD1w     = (const float*)d_in[7];
    const float* sD1b     = (const float*)d_in[8];
    const float* cw       = (const float*)d_in[9];
    const float* cb       = (const float*)d_in[10];
    const float* A_log    = (const float*)d_in[11];
    const float* Dp       = (const float*)d_in[12];
    const float* norm_w   = (const float*)d_in[13];
    const float* norm_f   = (const float*)d_in[14];
    const float* head_w   = (const float*)d_in[15];
    float* out = (float*)d_out;

    float *seq, *xn, *ab, *a, *bcd, *delta, *y, *w128;
    cudaGetSymbolAddress((void**)&seq,   g_seq);
    cudaGetSymbolAddress((void**)&xn,    g_xn);
    cudaGetSymbolAddress((void**)&ab,    g_ab);
    cudaGetSymbolAddress((void**)&a,     g_a);
    cudaGetSymbolAddress((void**)&bcd,   g_bcd);
    cudaGetSymbolAddress((void**)&delta, g_delta);
    cudaGetSymbolAddress((void**)&y,     g_y);
    cudaGetSymbolAddress((void**)&w128,  g_w128);

    k_embed<<<(T_TOK*DIN + 255)/256, 256>>>(tok, emb);
    k_build_w128<<<(NLAYER*128*DM + 255)/256, 256>>>(sB, sC, sD0);

    for (int i = 0; i < NLAYER; i++) {
        // x = rmsnorm(seq)
        k_rmsnorm<<<T_TOK, 256>>>(seq, norm_w + (long)i*DIN, xn);
        // ab = x @ in_proj^T   [T, 3072]
        {
            dim3 g(2*DM/128, T_TOK/128);
            k_sgemm<0><<<g, 256>>>(xn, in_proj + (long)i*2*DM*DIN, ab, nullptr,
                                   T_TOK, 2*DM, DIN, DIN, DIN, 2*DM);
        }
        // a = silu(causal depthwise conv(ab[:, :1536]))
        k_conv_silu<<<(T_TOK*DM + 255)/256, 256>>>(cw + (long)i*DM*KCONV, cb + (long)i*DM);
        // [Bm | Cm | a@sD0^T] = a @ w128^T   [T, 128]
        {
            dim3 g(1, T_TOK/128);
            k_sgemm<0><<<g, 256>>>(a, w128 + (long)i*128*DM, bcd, nullptr,
                                   T_TOK, 128, DM, DM, DM, 128);
        }
        // delta = softplus(dt @ sD1^T + b)   [T, 1536]
        {
            dim3 g(DM/128, T_TOK/128);
            k_sgemm<2><<<g, 256>>>(bcd + 32, sD1w + (long)i*DM*DD, delta,
                                   sD1b + (long)i*DM,
                                   T_TOK, DM, DD, 128, DD, DM);
        }
        // sequential scan + D-skip + gating -> y
        k_scan<<<(BATCH*DM)/16, 256>>>(A_log + (long)i*DM*DS, Dp + (long)i*DM);
        // seq += y @ out_proj^T
        {
            dim3 g(DIN/128, T_TOK/128);
            k_sgemm<1><<<g, 256>>>(y, out_proj + (long)i*DIN*DM, seq, nullptr,
                                   T_TOK, DIN, DM, DM, DM, DIN);
        }
    }

    // final norm + head
    k_rmsnorm<<<T_TOK, 256>>>(seq, norm_f, xn);
    {
        dim3 g(VOCAB/128, T_TOK/128);
        k_sgemm<0><<<g, 256>>>(xn, head_w, out, nullptr,
                               T_TOK, VOCAB, DIN, DIN, DIN, VOCAB);
    }
}

// round 5
// speedup vs baseline: 1.6154x; 1.6154x over previous
#include <cuda_runtime.h>
#include <cuda_bf16.h>
#include <math.h>
#include <stdint.h>

#define BATCH 2
#define SEQLEN 1024
#define T_TOK (BATCH*SEQLEN)     // 2048
#define DIN 768
#define DM 1536
#define DS 16
#define DD 96
#define KCONV 4
#define NLAYER 4
#define VOCAB 32000
#define EPSF 1e-6f

// ---------------- scratch (device globals: no allocation allowed) ----------------
__device__ float g_seq[T_TOK*DIN];
__device__ float g_xn[T_TOK*DIN];
__device__ float g_ab[T_TOK*2*DM];
__device__ float g_a[T_TOK*DM];
__device__ float g_bcd[T_TOK*128];      // cols 0-15 Bm, 16-31 Cm, 32-127 (a@sD0^T)
__device__ float g_delta[T_TOK*DM];
__device__ float g_y[T_TOK*DM];
__device__ float g_w128[NLAYER*128*DM]; // concat [sB;sC;sD0] per layer

__device__ __forceinline__ float siluf(float x) { return x / (1.f + __expf(-x)); }

// ======================= bf16 split-MMA helpers (sm_80+ base target) =========
__device__ __forceinline__ void mma_bf16(float* c, const uint32_t* a, const uint32_t* b) {
    asm volatile(
        "mma.sync.aligned.m16n8k16.row.col.f32.bf16.bf16.f32 "
        "{%0,%1,%2,%3}, {%4,%5,%6,%7}, {%8,%9}, {%0,%1,%2,%3};"
        : "+f"(c[0]), "+f"(c[1]), "+f"(c[2]), "+f"(c[3])
        : "r"(a[0]), "r"(a[1]), "r"(a[2]), "r"(a[3]), "r"(b[0]), "r"(b[1]));
}

// split pair (x,y) into packed bf16x2 hi and lo parts (error compensation)
__device__ __forceinline__ void split2(float x, float y, uint32_t& hi, uint32_t& lo) {
    __nv_bfloat16 hx = __float2bfloat16_rn(x);
    __nv_bfloat16 hy = __float2bfloat16_rn(y);
    float rx = x - __bfloat162float(hx);
    float ry = y - __bfloat162float(hy);
    __nv_bfloat162 h = __halves2bfloat162(hx, hy);
    __nv_bfloat162 l = __halves2bfloat162(__float2bfloat16_rn(rx), __float2bfloat16_rn(ry));
    hi = *(uint32_t*)&h;
    lo = *(uint32_t*)&l;
}

// ======================= tensor-core bf16x3 GEMM =======================
// C[M,N] (op)= A[M,K] @ W[N,K]^T.  128x128 CTA tile, BK=32, double-buffered.
// Operands split into bf16 hi+lo; acc += Ah*Bh + Ah*Bl + Al*Bh (fp32 acc).
// 8 warps: 2(M) x 4(N), each 64x32 via m16n8k16.
// EPI: 0 = store, 1 = accumulate (residual), 2 = softplus(acc + bias[n])
#define BKS 36                        // bf16 elems per tile row (32 + pad 4)
#define TILE_BF (128*BKS)             // bf16 elems per tile
#define T_U32 (TILE_BF/2)             // u32 words per tile
#define SMEM_MMA_BYTES (8*TILE_BF*2)  // 4 arrays x 2 buffers, bf16

template<int EPI>
__global__ void __launch_bounds__(256)
k_tgemm(const float* __restrict__ A, const float* __restrict__ W,
        float* __restrict__ C, const float* __restrict__ bias,
        int K, int lda, int ldw, int ldc)
{
    extern __shared__ uint32_t usm[];
    // u32 layout per buffer: [AH | AL | BH | BL], each T_U32 words
    int tid = threadIdx.x;
    int wid = tid >> 5;
    int lane = tid & 31;
    int g  = lane >> 2;      // 0..7
    int tg = lane & 3;       // 0..3
    int wm = wid >> 2;       // 0..1
    int wn = wid & 3;        // 0..3

    int bm = blockIdx.y * 128;
    int bn = blockIdx.x * 128;

    // global load mapping: 4 float4 per thread per matrix (128 rows x 8 float4)
    const float* gA[4]; const float* gW[4]; int sidx[4];
    #pragma unroll
    for (int q = 0; q < 4; q++) {
        int idx = tid + 256*q;
        int r = idx >> 3, cg = idx & 7;
        gA[q] = A + (size_t)(bm + r) * lda + cg*4;
        gW[q] = W + (size_t)(bn + r) * ldw + cg*4;
        sidx[q] = r*18 + cg*2;       // u32 index within tile
    }

    float acc[4][4][4];
    #pragma unroll
    for (int mi = 0; mi < 4; mi++)
        #pragma unroll
        for (int ni = 0; ni < 4; ni++)
            #pragma unroll
            for (int e = 0; e < 4; e++) acc[mi][ni][e] = 0.f;

    int nk = K >> 5;
    float4 ra[4], rw[4];

    // prologue: load + store chunk 0 into buffer 0
    #pragma unroll
    for (int q = 0; q < 4; q++) { ra[q] = *(const float4*)gA[q]; rw[q] = *(const float4*)gW[q]; }
    #pragma unroll
    for (int q = 0; q < 4; q++) {
        uint32_t h0,l0,h1,l1;
        split2(ra[q].x, ra[q].y, h0, l0);
        split2(ra[q].z, ra[q].w, h1, l1);
        usm[0*T_U32 + sidx[q]] = h0; usm[0*T_U32 + sidx[q] + 1] = h1;
        usm[1*T_U32 + sidx[q]] = l0; usm[1*T_U32 + sidx[q] + 1] = l1;
        split2(rw[q].x, rw[q].y, h0, l0);
        split2(rw[q].z, rw[q].w, h1, l1);
        usm[2*T_U32 + sidx[q]] = h0; usm[2*T_U32 + sidx[q] + 1] = h1;
        usm[3*T_U32 + sidx[q]] = l0; usm[3*T_U32 + sidx[q] + 1] = l1;
    }
    __syncthreads();

    for (int kt = 0; kt < nk; kt++) {
        int cur = kt & 1;
        if (kt + 1 < nk) {
            int k0 = (kt+1) * 32;
            #pragma unroll
            for (int q = 0; q < 4; q++) {
                ra[q] = *(const float4*)(gA[q] + k0);
                rw[q] = *(const float4*)(gW[q] + k0);
            }
        }

        const uint32_t* uAH = usm + cur*4*T_U32 + 0*T_U32;
        const uint32_t* uAL = uAH + T_U32;
        const uint32_t* uBH = uAH + 2*T_U32;
        const uint32_t* uBL = uAH + 3*T_U32;

        #pragma unroll
        for (int ks = 0; ks < 2; ks++) {
            int k0 = ks*8;          // u32 offset (16 bf16)
            uint32_t ah[4][4], al[4][4], bh[4][2], bl[4][2];
            #pragma unroll
            for (int mi = 0; mi < 4; mi++) {
                int r0 = (wm*64 + mi*16 + g)*18;
                int r1 = r0 + 8*18;
                ah[mi][0] = uAH[r0 + k0 + tg];     ah[mi][1] = uAH[r1 + k0 + tg];
                ah[mi][2] = uAH[r0 + k0 + 4 + tg]; ah[mi][3] = uAH[r1 + k0 + 4 + tg];
                al[mi][0] = uAL[r0 + k0 + tg];     al[mi][1] = uAL[r1 + k0 + tg];
                al[mi][2] = uAL[r0 + k0 + 4 + tg]; al[mi][3] = uAL[r1 + k0 + 4 + tg];
            }
            #pragma unroll
            for (int ni = 0; ni < 4; ni++) {
                int c0 = (wn*32 + ni*8 + g)*18;
                bh[ni][0] = uBH[c0 + k0 + tg]; bh[ni][1] = uBH[c0 + k0 + 4 + tg];
                bl[ni][0] = uBL[c0 + k0 + tg]; bl[ni][1] = uBL[c0 + k0 + 4 + tg];
            }
            #pragma unroll
            for (int mi = 0; mi < 4; mi++)
                #pragma unroll
                for (int ni = 0; ni < 4; ni++) {
                    mma_bf16(acc[mi][ni], ah[mi], bh[ni]);
                    mma_bf16(acc[mi][ni], ah[mi], bl[ni]);
                    mma_bf16(acc[mi][ni], al[mi], bh[ni]);
                }
        }

        if (kt + 1 < nk) {
            int nxt = (kt+1) & 1;
            uint32_t* w = usm + nxt*4*T_U32;
            __syncthreads();
            #pragma unroll
            for (int q = 0; q < 4; q++) {
                uint32_t h0,l0,h1,l1;
                split2(ra[q].x, ra[q].y, h0, l0);
                split2(ra[q].z, ra[q].w, h1, l1);
                w[0*T_U32 + sidx[q]] = h0; w[0*T_U32 + sidx[q] + 1] = h1;
                w[1*T_U32 + sidx[q]] = l0; w[1*T_U32 + sidx[q] + 1] = l1;
                split2(rw[q].x, rw[q].y, h0, l0);
                split2(rw[q].z, rw[q].w, h1, l1);
                w[2*T_U32 + sidx[q]] = h0; w[2*T_U32 + sidx[q] + 1] = h1;
                w[3*T_U32 + sidx[q]] = l0; w[3*T_U32 + sidx[q] + 1] = l1;
            }
            __syncthreads();
        }
    }

    // epilogue
    #pragma unroll
    for (int mi = 0; mi < 4; mi++) {
        int r0 = bm + wm*64 + mi*16 + g;
        #pragma unroll
        for (int ni = 0; ni < 4; ni++) {
            int c0 = bn + wn*32 + ni*8 + tg*2;
            float2 v0 = make_float2(acc[mi][ni][0], acc[mi][ni][1]);
            float2 v1 = make_float2(acc[mi][ni][2], acc[mi][ni][3]);
            float* p0 = C + (size_t)r0 * ldc + c0;
            float* p1 = C + (size_t)(r0+8) * ldc + c0;
            if (EPI == 0) {
                *(float2*)p0 = v0;
                *(float2*)p1 = v1;
            } else if (EPI == 1) {
                float2 o0 = *(float2*)p0, o1 = *(float2*)p1;
                o0.x += v0.x; o0.y += v0.y; o1.x += v1.x; o1.y += v1.y;
                *(float2*)p0 = o0;
                *(float2*)p1 = o1;
            } else {
                float b0 = bias[c0], b1 = bias[c0+1];
                float s0 = v0.x + b0, s1 = v0.y + b1, s2 = v1.x + b0, s3 = v1.y + b1;
                v0.x = (s0 > 20.f) ? s0 : log1pf(__expf(s0));
                v0.y = (s1 > 20.f) ? s1 : log1pf(__expf(s1));
                v1.x = (s2 > 20.f) ? s2 : log1pf(__expf(s2));
                v1.y = (s3 > 20.f) ? s3 : log1pf(__expf(s3));
                *(float2*)p0 = v0;
                *(float2*)p1 = v1;
            }
        }
    }
}

// ---------------- embedding gather ----------------
__global__ void k_embed(const int* __restrict__ tok, const float* __restrict__ emb) {
    int i = blockIdx.x*blockDim.x + threadIdx.x;
    if (i >= T_TOK*DIN) return;
    int t = i / DIN, c = i % DIN;
    g_seq[i] = emb[(long)tok[t]*DIN + c];
}

// ---------------- rmsnorm ----------------
__global__ void k_rmsnorm(const float* __restrict__ x, const float* __restrict__ w,
                          float* __restrict__ out) {
    __shared__ float red[256];
    int t = blockIdx.x;
    const float* xr = x + (long)t*DIN;
    float s = 0.f;
    for (int c = threadIdx.x; c < DIN; c += 256) { float v = xr[c]; s += v*v; }
    red[threadIdx.x] = s; __syncthreads();
    for (int o = 128; o > 0; o >>= 1) {
        if (threadIdx.x < o) red[threadIdx.x] += red[threadIdx.x+o];
        __syncthreads();
    }
    float inv = rsqrtf(red[0] * (1.f/DIN) + EPSF);
    for (int c = threadIdx.x; c < DIN; c += 256) out[(long)t*DIN + c] = xr[c]*inv*w[c];
}

// ---------------- concat [sB;sC;sD0] ----------------
__global__ void k_build_w128(const float* __restrict__ sB, const float* __restrict__ sC,
                             const float* __restrict__ sD0) {
    int i = blockIdx.x*blockDim.x + threadIdx.x;
    if (i >= NLAYER*128*DM) return;
    int l = i / (128*DM);
    int r = (i / DM) % 128;
    int k = i % DM;
    float v;
    if (r < 16)       v = sB[((long)l*16 + r)*DM + k];
    else if (r < 32)  v = sC[((long)l*16 + (r-16))*DM + k];
    else              v = sD0[((long)l*96 + (r-32))*DM + k];
    g_w128[i] = v;
}

// ---------------- depthwise causal conv (K=4) + silu ----------------
__global__ void k_conv_silu(const float* __restrict__ cw, const float* __restrict__ cb) {
    int i = blockIdx.x*blockDim.x + threadIdx.x;
    if (i >= T_TOK*DM) return;
    int t = i / DM, d = i % DM;
    int l = t % SEQLEN;
    float acc = cb[d];
    #pragma unroll
    for (int j = 0; j < KCONV; j++) {
        int lj = l - (KCONV-1) + j;
        if (lj >= 0) acc += cw[d*KCONV + j] * g_ab[(long)(t - (KCONV-1) + j)*(2*DM) + d];
    }
    g_a[i] = siluf(acc);
}

// ---------------- SSM scan: 4 threads per (b,d), 4 states each ----------------
__global__ void k_scan(const float* __restrict__ A_log, const float* __restrict__ Dp) {
    int gt = blockIdx.x*blockDim.x + threadIdx.x;   // 0 .. BATCH*DM*4-1
    int grp = gt >> 2;
    int sq = gt & 3;
    int b = grp / DM, d = grp % DM;
    float Ads[4], h[4];
    #pragma unroll
    for (int j = 0; j < 4; j++) {
        Ads[j] = -__expf(A_log[d*DS + sq*4 + j]);
        h[j] = 0.f;
    }
    float Dd = Dp[d];
    int tbase = b * SEQLEN;
    for (int l = 0; l < SEQLEN; l++) {
        int t = tbase + l;
        float dv = g_delta[(size_t)t*DM + d];
        float av = g_a[(size_t)t*DM + d];
        float4 bm = *(const float4*)&g_bcd[t*128 + sq*4];
        float4 cm = *(const float4*)&g_bcd[t*128 + 16 + sq*4];
        float dva = dv * av;
        float e0 = __expf(dv*Ads[0]), e1 = __expf(dv*Ads[1]);
        float e2 = __expf(dv*Ads[2]), e3 = __expf(dv*Ads[3]);
        h[0] = fmaf(e0, h[0], dva*bm.x);
        h[1] = fmaf(e1, h[1], dva*bm.y);
        h[2] = fmaf(e2, h[2], dva*bm.z);
        h[3] = fmaf(e3, h[3], dva*bm.w);
        float y = h[0]*cm.x + h[1]*cm.y + h[2]*cm.z + h[3]*cm.w;
        y += __shfl_xor_sync(0xffffffffu, y, 1);
        y += __shfl_xor_sync(0xffffffffu, y, 2);
        if (sq == 0) {
            float bg = g_ab[(size_t)t*(2*DM) + DM + d];
            g_y[(size_t)t*DM + d] = (y + Dd*av) * siluf(bg);
        }
    }
}

// ---------------- host launcher ----------------
extern "C" void kernel_launch(void* const* d_in, const int* in_sizes, int n_in,
                              void* d_out, int out_size) {
    const int*   tok      = (const int*)  d_in[0];
    const float* emb      = (const float*)d_in[1];
    const float* in_proj  = (const float*)d_in[2];
    const float* out_proj = (const float*)d_in[3];
    const float* sB       = (const float*)d_in[4];
    const float* sC       = (const float*)d_in[5];
    const float* sD0      = (const float*)d_in[6];
    const float* sD1w     = (const float*)d_in[7];
    const float* sD1b     = (const float*)d_in[8];
    const float* cw       = (const float*)d_in[9];
    const float* cb       = (const float*)d_in[10];
    const float* A_log    = (const float*)d_in[11];
    const float* Dp       = (const float*)d_in[12];
    const float* norm_w   = (const float*)d_in[13];
    const float* norm_f   = (const float*)d_in[14];
    const float* head_w   = (const float*)d_in[15];
    float* out = (float*)d_out;

    float *seq, *xn, *ab, *a, *bcd, *delta, *y, *w128;
    cudaGetSymbolAddress((void**)&seq,   g_seq);
    cudaGetSymbolAddress((void**)&xn,    g_xn);
    cudaGetSymbolAddress((void**)&ab,    g_ab);
    cudaGetSymbolAddress((void**)&a,     g_a);
    cudaGetSymbolAddress((void**)&bcd,   g_bcd);
    cudaGetSymbolAddress((void**)&delta, g_delta);
    cudaGetSymbolAddress((void**)&y,     g_y);
    cudaGetSymbolAddress((void**)&w128,  g_w128);

    static bool attr_done = false;
    if (!attr_done) {
        cudaFuncSetAttribute(k_tgemm<0>, cudaFuncAttributeMaxDynamicSharedMemorySize, SMEM_MMA_BYTES);
        cudaFuncSetAttribute(k_tgemm<1>, cudaFuncAttributeMaxDynamicSharedMemorySize, SMEM_MMA_BYTES);
        cudaFuncSetAttribute(k_tgemm<2>, cudaFuncAttributeMaxDynamicSharedMemorySize, SMEM_MMA_BYTES);
        attr_done = true;
    }

    k_embed<<<(T_TOK*DIN + 255)/256, 256>>>(tok, emb);
    k_build_w128<<<(NLAYER*128*DM + 255)/256, 256>>>(sB, sC, sD0);

    for (int i = 0; i < NLAYER; i++) {
        k_rmsnorm<<<T_TOK, 256>>>(seq, norm_w + (long)i*DIN, xn);
        // ab = x @ in_proj^T   [T, 3072]
        {
            dim3 g(2*DM/128, T_TOK/128);
            k_tgemm<0><<<g, 256, SMEM_MMA_BYTES>>>(xn, in_proj + (long)i*2*DM*DIN, ab, nullptr,
                                                   DIN, DIN, DIN, 2*DM);
        }
        k_conv_silu<<<(T_TOK*DM + 255)/256, 256>>>(cw + (long)i*DM*KCONV, cb + (long)i*DM);
        // [Bm | Cm | a@sD0^T] = a @ w128^T   [T, 128]
        {
            dim3 g(1, T_TOK/128);
            k_tgemm<0><<<g, 256, SMEM_MMA_BYTES>>>(a, w128 + (long)i*128*DM, bcd, nullptr,
                                                   DM, DM, DM, 128);
        }
        // delta = softplus(dt @ sD1^T + b)   [T, 1536]
        {
            dim3 g(DM/128, T_TOK/128);
            k_tgemm<2><<<g, 256, SMEM_MMA_BYTES>>>(bcd + 32, sD1w + (long)i*DM*DD, delta,
                                                   sD1b + (long)i*DM, DD, 128, DD, DM);
        }
        k_scan<<<(BATCH*DM*4)/256, 256>>>(A_log + (long)i*DM*DS, Dp + (long)i*DM);
        // seq += y @ out_proj^T
        {
            dim3 g(DIN/128, T_TOK/128);
            k_tgemm<1><<<g, 256, SMEM_MMA_BYTES>>>(y, out_proj + (long)i*DIN*DM, seq, nullptr,
                                                   DM, DM, DM, DIN);
        }
    }

    k_rmsnorm<<<T_TOK, 256>>>(seq, norm_f, xn);
    {
        dim3 g(VOCAB/128, T_TOK/128);
        k_tgemm<0><<<g, 256, SMEM_MMA_BYTES>>>(xn, head_w, out, nullptr,
                                               DIN, DIN, DIN, VOCAB);
    }
}

// round 6
// speedup vs baseline: 2.4870x; 1.5396x over previous
#include <cuda_runtime.h>
#include <cuda_bf16.h>
#include <math.h>
#include <stdint.h>

#define BATCH 2
#define SEQLEN 1024
#define T_TOK (BATCH*SEQLEN)     // 2048
#define DIN 768
#define DM 1536
#define DS 16
#define DD 96
#define KCONV 4
#define NLAYER 4
#define VOCAB 32000
#define EPSF 1e-6f

// ---------------- scratch (device globals: no allocation allowed) ----------------
__device__ float g_seq[T_TOK*DIN];
__device__ float g_xn[T_TOK*DIN];
__device__ float g_ab[T_TOK*2*DM];
__device__ float g_a[T_TOK*DM];
__device__ float g_bcd[T_TOK*128];      // cols 0-15 Bm, 16-31 Cm, 32-127 (a@sD0^T)
__device__ float g_delta[T_TOK*DM];
__device__ float g_y[T_TOK*DM];
__device__ float g_w128[NLAYER*128*DM]; // concat [sB;sC;sD0] per layer

__device__ __forceinline__ float siluf(float x) { return x / (1.f + __expf(-x)); }

// ======================= bf16 split-MMA helpers (sm_80+ base target) =========
__device__ __forceinline__ void mma_bf16(float* c, const uint32_t* a, const uint32_t* b) {
    asm volatile(
        "mma.sync.aligned.m16n8k16.row.col.f32.bf16.bf16.f32 "
        "{%0,%1,%2,%3}, {%4,%5,%6,%7}, {%8,%9}, {%0,%1,%2,%3};"
        : "+f"(c[0]), "+f"(c[1]), "+f"(c[2]), "+f"(c[3])
        : "r"(a[0]), "r"(a[1]), "r"(a[2]), "r"(a[3]), "r"(b[0]), "r"(b[1]));
}

// split pair (x,y) into packed bf16x2 hi and lo parts (error compensation)
__device__ __forceinline__ void split2(float x, float y, uint32_t& hi, uint32_t& lo) {
    __nv_bfloat16 hx = __float2bfloat16_rn(x);
    __nv_bfloat16 hy = __float2bfloat16_rn(y);
    float rx = x - __bfloat162float(hx);
    float ry = y - __bfloat162float(hy);
    __nv_bfloat162 h = __halves2bfloat162(hx, hy);
    __nv_bfloat162 l = __halves2bfloat162(__float2bfloat16_rn(rx), __float2bfloat16_rn(ry));
    hi = *(uint32_t*)&h;
    lo = *(uint32_t*)&l;
}

// ======================= tensor-core bf16x3 GEMM =======================
// C[M,N] (op)= A[M,K] @ W[N,K]^T.  128x128 CTA tile, BK=32, double-buffered.
// Operands split into bf16 hi+lo; acc += Ah*Bh + Ah*Bl + Al*Bh (fp32 acc).
// 8 warps: 2(M) x 4(N), each 64x32 via m16n8k16.
// EPI: 0 = store, 1 = accumulate (residual), 2 = softplus(acc + bias[n])
#define BKS 36                        // bf16 elems per tile row (32 + pad 4)
#define TILE_BF (128*BKS)             // bf16 elems per tile
#define T_U32 (TILE_BF/2)             // u32 words per tile
#define SMEM_MMA_BYTES (8*TILE_BF*2)  // 4 arrays x 2 buffers, bf16

template<int EPI>
__global__ void __launch_bounds__(256)
k_tgemm(const float* __restrict__ A, const float* __restrict__ W,
        float* __restrict__ C, const float* __restrict__ bias,
        int K, int lda, int ldw, int ldc)
{
    extern __shared__ uint32_t usm[];
    // u32 layout per buffer: [AH | AL | BH | BL], each T_U32 words
    int tid = threadIdx.x;
    int wid = tid >> 5;
    int lane = tid & 31;
    int g  = lane >> 2;      // 0..7
    int tg = lane & 3;       // 0..3
    int wm = wid >> 2;       // 0..1
    int wn = wid & 3;        // 0..3

    int bm = blockIdx.y * 128;
    int bn = blockIdx.x * 128;

    // global load mapping: 4 float4 per thread per matrix (128 rows x 8 float4)
    const float* gA[4]; const float* gW[4]; int sidx[4];
    #pragma unroll
    for (int q = 0; q < 4; q++) {
        int idx = tid + 256*q;
        int r = idx >> 3, cg = idx & 7;
        gA[q] = A + (size_t)(bm + r) * lda + cg*4;
        gW[q] = W + (size_t)(bn + r) * ldw + cg*4;
        sidx[q] = r*18 + cg*2;       // u32 index within tile
    }

    float acc[4][4][4];
    #pragma unroll
    for (int mi = 0; mi < 4; mi++)
        #pragma unroll
        for (int ni = 0; ni < 4; ni++)
            #pragma unroll
            for (int e = 0; e < 4; e++) acc[mi][ni][e] = 0.f;

    int nk = K >> 5;
    float4 ra[4], rw[4];

    // prologue: load + store chunk 0 into buffer 0
    #pragma unroll
    for (int q = 0; q < 4; q++) { ra[q] = *(const float4*)gA[q]; rw[q] = *(const float4*)gW[q]; }
    #pragma unroll
    for (int q = 0; q < 4; q++) {
        uint32_t h0,l0,h1,l1;
        split2(ra[q].x, ra[q].y, h0, l0);
        split2(ra[q].z, ra[q].w, h1, l1);
        usm[0*T_U32 + sidx[q]] = h0; usm[0*T_U32 + sidx[q] + 1] = h1;
        usm[1*T_U32 + sidx[q]] = l0; usm[1*T_U32 + sidx[q] + 1] = l1;
        split2(rw[q].x, rw[q].y, h0, l0);
        split2(rw[q].z, rw[q].w, h1, l1);
        usm[2*T_U32 + sidx[q]] = h0; usm[2*T_U32 + sidx[q] + 1] = h1;
        usm[3*T_U32 + sidx[q]] = l0; usm[3*T_U32 + sidx[q] + 1] = l1;
    }
    __syncthreads();

    for (int kt = 0; kt < nk; kt++) {
        int cur = kt & 1;
        if (kt + 1 < nk) {
            int k0 = (kt+1) * 32;
            #pragma unroll
            for (int q = 0; q < 4; q++) {
                ra[q] = *(const float4*)(gA[q] + k0);
                rw[q] = *(const float4*)(gW[q] + k0);
            }
        }

        const uint32_t* uAH = usm + cur*4*T_U32 + 0*T_U32;
        const uint32_t* uAL = uAH + T_U32;
        const uint32_t* uBH = uAH + 2*T_U32;
        const uint32_t* uBL = uAH + 3*T_U32;

        #pragma unroll
        for (int ks = 0; ks < 2; ks++) {
            int k0 = ks*8;          // u32 offset (16 bf16)
            uint32_t ah[4][4], al[4][4], bh[4][2], bl[4][2];
            #pragma unroll
            for (int mi = 0; mi < 4; mi++) {
                int r0 = (wm*64 + mi*16 + g)*18;
                int r1 = r0 + 8*18;
                ah[mi][0] = uAH[r0 + k0 + tg];     ah[mi][1] = uAH[r1 + k0 + tg];
                ah[mi][2] = uAH[r0 + k0 + 4 + tg]; ah[mi][3] = uAH[r1 + k0 + 4 + tg];
                al[mi][0] = uAL[r0 + k0 + tg];     al[mi][1] = uAL[r1 + k0 + tg];
                al[mi][2] = uAL[r0 + k0 + 4 + tg]; al[mi][3] = uAL[r1 + k0 + 4 + tg];
            }
            #pragma unroll
            for (int ni = 0; ni < 4; ni++) {
                int c0 = (wn*32 + ni*8 + g)*18;
                bh[ni][0] = uBH[c0 + k0 + tg]; bh[ni][1] = uBH[c0 + k0 + 4 + tg];
                bl[ni][0] = uBL[c0 + k0 + tg]; bl[ni][1] = uBL[c0 + k0 + 4 + tg];
            }
            #pragma unroll
            for (int mi = 0; mi < 4; mi++)
                #pragma unroll
                for (int ni = 0; ni < 4; ni++) {
                    mma_bf16(acc[mi][ni], ah[mi], bh[ni]);
                    mma_bf16(acc[mi][ni], ah[mi], bl[ni]);
                    mma_bf16(acc[mi][ni], al[mi], bh[ni]);
                }
        }

        if (kt + 1 < nk) {
            int nxt = (kt+1) & 1;
            uint32_t* w = usm + nxt*4*T_U32;
            __syncthreads();
            #pragma unroll
            for (int q = 0; q < 4; q++) {
                uint32_t h0,l0,h1,l1;
                split2(ra[q].x, ra[q].y, h0, l0);
                split2(ra[q].z, ra[q].w, h1, l1);
                w[0*T_U32 + sidx[q]] = h0; w[0*T_U32 + sidx[q] + 1] = h1;
                w[1*T_U32 + sidx[q]] = l0; w[1*T_U32 + sidx[q] + 1] = l1;
                split2(rw[q].x, rw[q].y, h0, l0);
                split2(rw[q].z, rw[q].w, h1, l1);
                w[2*T_U32 + sidx[q]] = h0; w[2*T_U32 + sidx[q] + 1] = h1;
                w[3*T_U32 + sidx[q]] = l0; w[3*T_U32 + sidx[q] + 1] = l1;
            }
            __syncthreads();
        }
    }

    // epilogue
    #pragma unroll
    for (int mi = 0; mi < 4; mi++) {
        int r0 = bm + wm*64 + mi*16 + g;
        #pragma unroll
        for (int ni = 0; ni < 4; ni++) {
            int c0 = bn + wn*32 + ni*8 + tg*2;
            float2 v0 = make_float2(acc[mi][ni][0], acc[mi][ni][1]);
            float2 v1 = make_float2(acc[mi][ni][2], acc[mi][ni][3]);
            float* p0 = C + (size_t)r0 * ldc + c0;
            float* p1 = C + (size_t)(r0+8) * ldc + c0;
            if (EPI == 0) {
                *(float2*)p0 = v0;
                *(float2*)p1 = v1;
            } else if (EPI == 1) {
                float2 o0 = *(float2*)p0, o1 = *(float2*)p1;
                o0.x += v0.x; o0.y += v0.y; o1.x += v1.x; o1.y += v1.y;
                *(float2*)p0 = o0;
                *(float2*)p1 = o1;
            } else {
                float b0 = bias[c0], b1 = bias[c0+1];
                float s0 = v0.x + b0, s1 = v0.y + b1, s2 = v1.x + b0, s3 = v1.y + b1;
                v0.x = (s0 > 20.f) ? s0 : log1pf(__expf(s0));
                v0.y = (s1 > 20.f) ? s1 : log1pf(__expf(s1));
                v1.x = (s2 > 20.f) ? s2 : log1pf(__expf(s2));
                v1.y = (s3 > 20.f) ? s3 : log1pf(__expf(s3));
                *(float2*)p0 = v0;
                *(float2*)p1 = v1;
            }
        }
    }
}

// ---------------- embedding gather ----------------
__global__ void k_embed(const int* __restrict__ tok, const float* __restrict__ emb) {
    int i = blockIdx.x*blockDim.x + threadIdx.x;
    if (i >= T_TOK*DIN) return;
    int t = i / DIN, c = i % DIN;
    g_seq[i] = emb[(long)tok[t]*DIN + c];
}

// ---------------- rmsnorm ----------------
__global__ void k_rmsnorm(const float* __restrict__ x, const float* __restrict__ w,
                          float* __restrict__ out) {
    __shared__ float red[256];
    int t = blockIdx.x;
    const float* xr = x + (long)t*DIN;
    float s = 0.f;
    for (int c = threadIdx.x; c < DIN; c += 256) { float v = xr[c]; s += v*v; }
    red[threadIdx.x] = s; __syncthreads();
    for (int o = 128; o > 0; o >>= 1) {
        if (threadIdx.x < o) red[threadIdx.x] += red[threadIdx.x+o];
        __syncthreads();
    }
    float inv = rsqrtf(red[0] * (1.f/DIN) + EPSF);
    for (int c = threadIdx.x; c < DIN; c += 256) out[(long)t*DIN + c] = xr[c]*inv*w[c];
}

// ---------------- concat [sB;sC;sD0] ----------------
__global__ void k_build_w128(const float* __restrict__ sB, const float* __restrict__ sC,
                             const float* __restrict__ sD0) {
    int i = blockIdx.x*blockDim.x + threadIdx.x;
    if (i >= NLAYER*128*DM) return;
    int l = i / (128*DM);
    int r = (i / DM) % 128;
    int k = i % DM;
    float v;
    if (r < 16)       v = sB[((long)l*16 + r)*DM + k];
    else if (r < 32)  v = sC[((long)l*16 + (r-16))*DM + k];
    else              v = sD0[((long)l*96 + (r-32))*DM + k];
    g_w128[i] = v;
}

// ---------------- depthwise causal conv (K=4) + silu ----------------
__global__ void k_conv_silu(const float* __restrict__ cw, const float* __restrict__ cb) {
    int i = blockIdx.x*blockDim.x + threadIdx.x;
    if (i >= T_TOK*DM) return;
    int t = i / DM, d = i % DM;
    int l = t % SEQLEN;
    float acc = cb[d];
    #pragma unroll
    for (int j = 0; j < KCONV; j++) {
        int lj = l - (KCONV-1) + j;
        if (lj >= 0) acc += cw[d*KCONV + j] * g_ab[(long)(t - (KCONV-1) + j)*(2*DM) + d];
    }
    g_a[i] = siluf(acc);
}

// ---------------- SSM scan: block-cooperative, SMEM-staged, double-buffered --
// block = 128 threads = 32 d-channels x 4 threads (4 states each), one b/block.
// grid = BATCH * DM/32 = 96 blocks. Timesteps in chunks of SCH=16:
// prefetch chunk c+1 into registers while computing chunk c from SMEM.
#define SCH 16
__global__ void __launch_bounds__(128)
k_scan(const float* __restrict__ A_log, const float* __restrict__ Dp) {
    __shared__ float sdv[2][SCH][32];
    __shared__ float sav[2][SCH][32];
    __shared__ float sbc[2][SCH][32];   // cols 0-15 B, 16-31 C
    __shared__ float sbg[2][SCH][32];
    __shared__ float sy[SCH][32];

    int tid = threadIdx.x;
    int dq = tid >> 2;          // 0..31 channel within block
    int sq = tid & 3;           // state quad
    int b  = blockIdx.x / (DM/32);
    int d0 = (blockIdx.x % (DM/32)) * 32;
    int d  = d0 + dq;

    float Ads[4], h[4];
    #pragma unroll
    for (int j = 0; j < 4; j++) {
        Ads[j] = -__expf(A_log[d*DS + sq*4 + j]);
        h[j] = 0.f;
    }
    float Dd = Dp[d];

    // staging indices: idx = tid + 128*q, tt = idx>>5, dd = idx&31 (coalesced 128B)
    int tt0[4], dd0[4];
    #pragma unroll
    for (int q = 0; q < 4; q++) { int idx = tid + 128*q; tt0[q] = idx >> 5; dd0[q] = idx & 31; }

    float rdv[4], rav[4], rbc[4], rbg[4];
    const size_t tb = (size_t)b * SEQLEN;

    // prologue: load chunk 0
    #pragma unroll
    for (int q = 0; q < 4; q++) {
        size_t t = tb + tt0[q];
        rdv[q] = g_delta[t*DM + d0 + dd0[q]];
        rav[q] = g_a[t*DM + d0 + dd0[q]];
        rbc[q] = g_bcd[t*128 + dd0[q]];
        rbg[q] = g_ab[t*(2*DM) + DM + d0 + dd0[q]];
    }
    #pragma unroll
    for (int q = 0; q < 4; q++) {
        sdv[0][tt0[q]][dd0[q]] = rdv[q];
        sav[0][tt0[q]][dd0[q]] = rav[q];
        sbc[0][tt0[q]][dd0[q]] = rbc[q];
        sbg[0][tt0[q]][dd0[q]] = rbg[q];
    }
    __syncthreads();

    const int NCH = SEQLEN / SCH;
    for (int c = 0; c < NCH; c++) {
        int cur = c & 1;
        // prefetch next chunk into registers (overlaps with compute below)
        if (c + 1 < NCH) {
            #pragma unroll
            for (int q = 0; q < 4; q++) {
                size_t t = tb + (size_t)(c+1)*SCH + tt0[q];
                rdv[q] = g_delta[t*DM + d0 + dd0[q]];
                rav[q] = g_a[t*DM + d0 + dd0[q]];
                rbc[q] = g_bcd[t*128 + dd0[q]];
                rbg[q] = g_ab[t*(2*DM) + DM + d0 + dd0[q]];
            }
        }

        // compute chunk c from SMEM
        #pragma unroll
        for (int tt = 0; tt < SCH; tt++) {
            float dv = sdv[cur][tt][dq];
            float av = sav[cur][tt][dq];
            float dva = dv * av;
            float bm0 = sbc[cur][tt][sq*4+0], bm1 = sbc[cur][tt][sq*4+1];
            float bm2 = sbc[cur][tt][sq*4+2], bm3 = sbc[cur][tt][sq*4+3];
            float cm0 = sbc[cur][tt][16+sq*4+0], cm1 = sbc[cur][tt][16+sq*4+1];
            float cm2 = sbc[cur][tt][16+sq*4+2], cm3 = sbc[cur][tt][16+sq*4+3];
            h[0] = fmaf(__expf(dv*Ads[0]), h[0], dva*bm0);
            h[1] = fmaf(__expf(dv*Ads[1]), h[1], dva*bm1);
            h[2] = fmaf(__expf(dv*Ads[2]), h[2], dva*bm2);
            h[3] = fmaf(__expf(dv*Ads[3]), h[3], dva*bm3);
            float y = h[0]*cm0 + h[1]*cm1 + h[2]*cm2 + h[3]*cm3;
            y += __shfl_xor_sync(0xffffffffu, y, 1);
            y += __shfl_xor_sync(0xffffffffu, y, 2);
            if (sq == 0) {
                float bg = sbg[cur][tt][dq];
                sy[tt][dq] = (y + Dd*av) * siluf(bg);
            }
        }
        __syncthreads();

        // coalesced writeback of y for chunk c
        #pragma unroll
        for (int q = 0; q < 4; q++) {
            size_t t = tb + (size_t)c*SCH + tt0[q];
            g_y[t*DM + d0 + dd0[q]] = sy[tt0[q]][dd0[q]];
        }

        // stage prefetched chunk into the other buffer
        if (c + 1 < NCH) {
            int nxt = cur ^ 1;
            #pragma unroll
            for (int q = 0; q < 4; q++) {
                sdv[nxt][tt0[q]][dd0[q]] = rdv[q];
                sav[nxt][tt0[q]][dd0[q]] = rav[q];
                sbc[nxt][tt0[q]][dd0[q]] = rbc[q];
                sbg[nxt][tt0[q]][dd0[q]] = rbg[q];
            }
            __syncthreads();
        }
    }
}

// ---------------- host launcher ----------------
extern "C" void kernel_launch(void* const* d_in, const int* in_sizes, int n_in,
                              void* d_out, int out_size) {
    const int*   tok      = (const int*)  d_in[0];
    const float* emb      = (const float*)d_in[1];
    const float* in_proj  = (const float*)d_in[2];
    const float* out_proj = (const float*)d_in[3];
    const float* sB       = (const float*)d_in[4];
    const float* sC       = (const float*)d_in[5];
    const float* sD0      = (const float*)d_in[6];
    const float* sD1w     = (const float*)d_in[7];
    const float* sD1b     = (const float*)d_in[8];
    const float* cw       = (const float*)d_in[9];
    const float* cb       = (const float*)d_in[10];
    const float* A_log    = (const float*)d_in[11];
    const float* Dp       = (const float*)d_in[12];
    const float* norm_w   = (const float*)d_in[13];
    const float* norm_f   = (const float*)d_in[14];
    const float* head_w   = (const float*)d_in[15];
    float* out = (float*)d_out;

    float *seq, *xn, *ab, *a, *bcd, *delta, *y, *w128;
    cudaGetSymbolAddress((void**)&seq,   g_seq);
    cudaGetSymbolAddress((void**)&xn,    g_xn);
    cudaGetSymbolAddress((void**)&ab,    g_ab);
    cudaGetSymbolAddress((void**)&a,     g_a);
    cudaGetSymbolAddress((void**)&bcd,   g_bcd);
    cudaGetSymbolAddress((void**)&delta, g_delta);
    cudaGetSymbolAddress((void**)&y,     g_y);
    cudaGetSymbolAddress((void**)&w128,  g_w128);

    static bool attr_done = false;
    if (!attr_done) {
        cudaFuncSetAttribute(k_tgemm<0>, cudaFuncAttributeMaxDynamicSharedMemorySize, SMEM_MMA_BYTES);
        cudaFuncSetAttribute(k_tgemm<1>, cudaFuncAttributeMaxDynamicSharedMemorySize, SMEM_MMA_BYTES);
        cudaFuncSetAttribute(k_tgemm<2>, cudaFuncAttributeMaxDynamicSharedMemorySize, SMEM_MMA_BYTES);
        attr_done = true;
    }

    k_embed<<<(T_TOK*DIN + 255)/256, 256>>>(tok, emb);
    k_build_w128<<<(NLAYER*128*DM + 255)/256, 256>>>(sB, sC, sD0);

    for (int i = 0; i < NLAYER; i++) {
        k_rmsnorm<<<T_TOK, 256>>>(seq, norm_w + (long)i*DIN, xn);
        // ab = x @ in_proj^T   [T, 3072]
        {
            dim3 g(2*DM/128, T_TOK/128);
            k_tgemm<0><<<g, 256, SMEM_MMA_BYTES>>>(xn, in_proj + (long)i*2*DM*DIN, ab, nullptr,
                                                   DIN, DIN, DIN, 2*DM);
        }
        k_conv_silu<<<(T_TOK*DM + 255)/256, 256>>>(cw + (long)i*DM*KCONV, cb + (long)i*DM);
        // [Bm | Cm | a@sD0^T] = a @ w128^T   [T, 128]
        {
            dim3 g(1, T_TOK/128);
            k_tgemm<0><<<g, 256, SMEM_MMA_BYTES>>>(a, w128 + (long)i*128*DM, bcd, nullptr,
                                                   DM, DM, DM, 128);
        }
        // delta = softplus(dt @ sD1^T + b)   [T, 1536]
        {
            dim3 g(DM/128, T_TOK/128);
            k_tgemm<2><<<g, 256, SMEM_MMA_BYTES>>>(bcd + 32, sD1w + (long)i*DM*DD, delta,
                                                   sD1b + (long)i*DM, DD, 128, DD, DM);
        }
        k_scan<<<BATCH*(DM/32), 128>>>(A_log + (long)i*DM*DS, Dp + (long)i*DM);
        // seq += y @ out_proj^T
        {
            dim3 g(DIN/128, T_TOK/128);
            k_tgemm<1><<<g, 256, SMEM_MMA_BYTES>>>(y, out_proj + (long)i*DIN*DM, seq, nullptr,
                                                   DM, DM, DM, DIN);
        }
    }

    k_rmsnorm<<<T_TOK, 256>>>(seq, norm_f, xn);
    {
        dim3 g(VOCAB/128, T_TOK/128);
        k_tgemm<0><<<g, 256, SMEM_MMA_BYTES>>>(xn, head_w, out, nullptr,
                                               DIN, DIN, DIN, VOCAB);
    }
}

// round 7
// speedup vs baseline: 2.7863x; 1.1203x over previous
#include <cuda_runtime.h>
#include <cuda_bf16.h>
#include <math.h>
#include <stdint.h>

#define BATCH 2
#define SEQLEN 1024
#define T_TOK (BATCH*SEQLEN)     // 2048
#define DIN 768
#define DM 1536
#define DS 16
#define DD 96
#define KCONV 4
#define NLAYER 4
#define VOCAB 32000
#define EPSF 1e-6f

// ---------------- fp32 scratch ----------------
__device__ float g_seq[T_TOK*DIN];
__device__ float g_ab[T_TOK*2*DM];
__device__ float g_a[T_TOK*DM];
__device__ float g_bcd[T_TOK*128];      // cols 0-15 Bm, 16-31 Cm (fp32, scan input)
__device__ float g_delta[T_TOK*DM];

// ---------------- bf16 split scratch (hi / lo) ----------------
__device__ __nv_bfloat16 g_xnh[T_TOK*DIN],  g_xnl[T_TOK*DIN];
__device__ __nv_bfloat16 g_ah [T_TOK*DM],   g_al [T_TOK*DM];
__device__ __nv_bfloat16 g_dth[T_TOK*DD],   g_dtl[T_TOK*DD];
__device__ __nv_bfloat16 g_yh [T_TOK*DM],   g_yl [T_TOK*DM];
__device__ __nv_bfloat16 g_wih[NLAYER*2*DM*DIN], g_wil[NLAYER*2*DM*DIN];
__device__ __nv_bfloat16 g_woh[NLAYER*DIN*DM],   g_wol[NLAYER*DIN*DM];
__device__ __nv_bfloat16 g_w128h[NLAYER*128*DM], g_w128l[NLAYER*128*DM];
__device__ __nv_bfloat16 g_sd1h[NLAYER*DM*DD],   g_sd1l[NLAYER*DM*DD];
__device__ __nv_bfloat16 g_hwh[VOCAB*DIN],       g_hwl[VOCAB*DIN];

__device__ __forceinline__ float siluf(float x) { return x / (1.f + __expf(-x)); }

// split pair (x,y) into packed bf16x2 hi and lo parts (error compensation)
__device__ __forceinline__ void split2(float x, float y, uint32_t& hi, uint32_t& lo) {
    __nv_bfloat16 hx = __float2bfloat16_rn(x);
    __nv_bfloat16 hy = __float2bfloat16_rn(y);
    float rx = x - __bfloat162float(hx);
    float ry = y - __bfloat162float(hy);
    __nv_bfloat162 h = __halves2bfloat162(hx, hy);
    __nv_bfloat162 l = __halves2bfloat162(__float2bfloat16_rn(rx), __float2bfloat16_rn(ry));
    hi = *(uint32_t*)&h;
    lo = *(uint32_t*)&l;
}

__device__ __forceinline__ uint32_t smem_u32(const void* p) {
    uint32_t a;
    asm("{ .reg .u64 t; cvta.to.shared.u64 t, %1; cvt.u32.u64 %0, t; }" : "=r"(a) : "l"(p));
    return a;
}
__device__ __forceinline__ void cpa16(uint32_t dst, const void* src) {
    asm volatile("cp.async.cg.shared.global [%0], [%1], 16;" :: "r"(dst), "l"(src));
}
#define CP_COMMIT() asm volatile("cp.async.commit_group;")
#define CP_WAIT0()  asm volatile("cp.async.wait_group 0;")

__device__ __forceinline__ void ldsm4(uint32_t& r0, uint32_t& r1, uint32_t& r2, uint32_t& r3,
                                      uint32_t a) {
    asm volatile("ldmatrix.sync.aligned.m8n8.x4.shared.b16 {%0,%1,%2,%3}, [%4];"
                 : "=r"(r0), "=r"(r1), "=r"(r2), "=r"(r3) : "r"(a));
}
__device__ __forceinline__ void mma_bf16(float* c, const uint32_t* a, const uint32_t* b) {
    asm volatile(
        "mma.sync.aligned.m16n8k16.row.col.f32.bf16.bf16.f32 "
        "{%0,%1,%2,%3}, {%4,%5,%6,%7}, {%8,%9}, {%0,%1,%2,%3};"
        : "+f"(c[0]), "+f"(c[1]), "+f"(c[2]), "+f"(c[3])
        : "r"(a[0]), "r"(a[1]), "r"(a[2]), "r"(a[3]), "r"(b[0]), "r"(b[1]));
}

// ======================= bf16x3 GEMM: cp.async + ldmatrix =======================
// C[M,N] (op)= A[M,K] @ W[N,K]^T with A,W pre-split to bf16 hi/lo.
// acc += Ah*Bh + Ah*Bl + Al*Bh (fp32 acc). CTA 128x128, BK=32, 2-stage cp.async.
// 8 warps: 2(M) x 4(N), each 64x32 via m16n8k16, ldmatrix.x4 fragment loads.
// EPI: 0=store, 1=accumulate, 2=softplus(acc+bias[n]), 3=bcd (fp32 cols<32, split cols>=32)
#define ROWB 80                       // smem bytes per row: 32 bf16 (64B) + 16B pad
#define PARTB (128*ROWB)              // 10240 B per matrix part
#define STAGEB (4*PARTB)              // 40960 B per stage (Ah,Al,Bh,Bl)
#define SMEM_G (2*STAGEB)             // 81920 B

template<int EPI>
__global__ void __launch_bounds__(256, 2)
k_gemm(const __nv_bfloat16* __restrict__ Ah, const __nv_bfloat16* __restrict__ Al,
       const __nv_bfloat16* __restrict__ Bh, const __nv_bfloat16* __restrict__ Bl,
       float* __restrict__ C, const float* __restrict__ bias,
       __nv_bfloat16* __restrict__ dth, __nv_bfloat16* __restrict__ dtl,
       int K, int ldc)
{
    extern __shared__ char smc[];
    uint32_t sb = smem_u32(smc);
    int tid = threadIdx.x, wid = tid >> 5, lane = tid & 31;
    int wm = wid >> 2, wn = wid & 3;
    int bm = blockIdx.y * 128, bn = blockIdx.x * 128;

    // cp.async mapping: thread handles (row = tid>>1, chunks c0,c0+1) per part
    int crow = tid >> 1;
    int cch  = (tid & 1) * 2;          // 0 or 2
    const __nv_bfloat16* pAh = Ah + (size_t)(bm + crow)*K + cch*8;
    const __nv_bfloat16* pAl = Al + (size_t)(bm + crow)*K + cch*8;
    const __nv_bfloat16* pBh = Bh + (size_t)(bn + crow)*K + cch*8;
    const __nv_bfloat16* pBl = Bl + (size_t)(bn + crow)*K + cch*8;
    uint32_t sOff = crow*ROWB + cch*16;

    // ldmatrix lane address components
    uint32_t aoff = (uint32_t)(wm*64 + (lane & 15))*ROWB + (lane >> 4)*16;
    uint32_t boff = (uint32_t)(wn*32 + ((lane >> 4) & 1)*8 + (lane & 7))*ROWB
                  + ((lane >> 3) & 1)*16;

    float acc[4][4][4];
    #pragma unroll
    for (int mi = 0; mi < 4; mi++)
        #pragma unroll
        for (int ni = 0; ni < 4; ni++)
            #pragma unroll
            for (int e = 0; e < 4; e++) acc[mi][ni][e] = 0.f;

    int nk = K >> 5;

    // issue stage 0
    {
        uint32_t s = sb + sOff;
        cpa16(s + 0*PARTB,      pAh); cpa16(s + 0*PARTB + 16, pAh + 8);
        cpa16(s + 1*PARTB,      pAl); cpa16(s + 1*PARTB + 16, pAl + 8);
        cpa16(s + 2*PARTB,      pBh); cpa16(s + 2*PARTB + 16, pBh + 8);
        cpa16(s + 3*PARTB,      pBl); cpa16(s + 3*PARTB + 16, pBl + 8);
    }
    CP_COMMIT();

    for (int kt = 0; kt < nk; kt++) {
        int slot = kt & 1;
        CP_WAIT0();
        __syncthreads();
        if (kt + 1 < nk) {
            uint32_t s = sb + ((kt+1) & 1)*STAGEB + sOff;
            size_t ko = (size_t)(kt+1)*32;
            cpa16(s + 0*PARTB,      pAh + ko); cpa16(s + 0*PARTB + 16, pAh + ko + 8);
            cpa16(s + 1*PARTB,      pAl + ko); cpa16(s + 1*PARTB + 16, pAl + ko + 8);
            cpa16(s + 2*PARTB,      pBh + ko); cpa16(s + 2*PARTB + 16, pBh + ko + 8);
            cpa16(s + 3*PARTB,      pBl + ko); cpa16(s + 3*PARTB + 16, pBl + ko + 8);
            CP_COMMIT();
        }

        uint32_t base = sb + slot*STAGEB;
        #pragma unroll
        for (int ks = 0; ks < 2; ks++) {
            uint32_t ksb = ks*32;
            uint32_t bh[4][2], bl[4][2];
            ldsm4(bh[0][0], bh[0][1], bh[1][0], bh[1][1], base + 2*PARTB + boff + ksb);
            ldsm4(bh[2][0], bh[2][1], bh[3][0], bh[3][1], base + 2*PARTB + boff + 16*ROWB + ksb);
            ldsm4(bl[0][0], bl[0][1], bl[1][0], bl[1][1], base + 3*PARTB + boff + ksb);
            ldsm4(bl[2][0], bl[2][1], bl[3][0], bl[3][1], base + 3*PARTB + boff + 16*ROWB + ksb);
            #pragma unroll
            for (int mi = 0; mi < 4; mi++) {
                uint32_t ah[4], al[4];
                ldsm4(ah[0], ah[1], ah[2], ah[3], base + 0*PARTB + aoff + mi*16*ROWB + ksb);
                ldsm4(al[0], al[1], al[2], al[3], base + 1*PARTB + aoff + mi*16*ROWB + ksb);
                #pragma unroll
                for (int ni = 0; ni < 4; ni++) {
                    mma_bf16(acc[mi][ni], ah, bh[ni]);
                    mma_bf16(acc[mi][ni], ah, bl[ni]);
                    mma_bf16(acc[mi][ni], al, bh[ni]);
                }
            }
        }
    }

    // epilogue
    int g  = lane >> 2, tg = lane & 3;
    #pragma unroll
    for (int mi = 0; mi < 4; mi++) {
        int r0 = bm + wm*64 + mi*16 + g;
        #pragma unroll
        for (int ni = 0; ni < 4; ni++) {
            int c0 = bn + wn*32 + ni*8 + tg*2;
            float2 v0 = make_float2(acc[mi][ni][0], acc[mi][ni][1]);
            float2 v1 = make_float2(acc[mi][ni][2], acc[mi][ni][3]);
            float* p0 = C + (size_t)r0 * ldc + c0;
            float* p1 = C + (size_t)(r0+8) * ldc + c0;
            if (EPI == 0) {
                *(float2*)p0 = v0;
                *(float2*)p1 = v1;
            } else if (EPI == 1) {
                float2 o0 = *(float2*)p0, o1 = *(float2*)p1;
                o0.x += v0.x; o0.y += v0.y; o1.x += v1.x; o1.y += v1.y;
                *(float2*)p0 = o0;
                *(float2*)p1 = o1;
            } else if (EPI == 2) {
                float b0 = bias[c0], b1 = bias[c0+1];
                float s0 = v0.x + b0, s1 = v0.y + b1, s2 = v1.x + b0, s3 = v1.y + b1;
                v0.x = (s0 > 20.f) ? s0 : log1pf(__expf(s0));
                v0.y = (s1 > 20.f) ? s1 : log1pf(__expf(s1));
                v1.x = (s2 > 20.f) ? s2 : log1pf(__expf(s2));
                v1.y = (s3 > 20.f) ? s3 : log1pf(__expf(s3));
                *(float2*)p0 = v0;
                *(float2*)p1 = v1;
            } else {
                // EPI==3: bcd. cols<32 -> fp32 B/C for scan; cols>=32 -> split dt
                if (c0 < 32) {
                    *(float2*)p0 = v0;
                    *(float2*)p1 = v1;
                } else {
                    uint32_t h, l;
                    split2(v0.x, v0.y, h, l);
                    ((uint32_t*)dth)[((size_t)r0*DD + c0 - 32) >> 1] = h;
                    ((uint32_t*)dtl)[((size_t)r0*DD + c0 - 32) >> 1] = l;
                    split2(v1.x, v1.y, h, l);
                    ((uint32_t*)dth)[((size_t)(r0+8)*DD + c0 - 32) >> 1] = h;
                    ((uint32_t*)dtl)[((size_t)(r0+8)*DD + c0 - 32) >> 1] = l;
                }
            }
        }
    }
}

// ---------------- weight split: fp32 -> bf16 hi/lo ----------------
__global__ void k_split(const float* __restrict__ src, __nv_bfloat16* __restrict__ h,
                        __nv_bfloat16* __restrict__ l, int n2) {
    int i = blockIdx.x*blockDim.x + threadIdx.x;
    if (i >= n2) return;
    float2 v = ((const float2*)src)[i];
    uint32_t hh, ll;
    split2(v.x, v.y, hh, ll);
    ((uint32_t*)h)[i] = hh;
    ((uint32_t*)l)[i] = ll;
}

// ---------------- embedding gather ----------------
__global__ void k_embed(const int* __restrict__ tok, const float* __restrict__ emb) {
    int i = blockIdx.x*blockDim.x + threadIdx.x;
    if (i >= T_TOK*DIN) return;
    int t = i / DIN, c = i % DIN;
    g_seq[i] = emb[(long)tok[t]*DIN + c];
}

// ---------------- rmsnorm -> split bf16 ----------------
__global__ void k_rmsnorm(const float* __restrict__ x, const float* __restrict__ w,
                          __nv_bfloat16* __restrict__ oh, __nv_bfloat16* __restrict__ ol) {
    __shared__ float red[256];
    int t = blockIdx.x;
    const float* xr = x + (long)t*DIN;
    float s = 0.f;
    for (int c = threadIdx.x; c < DIN; c += 256) { float v = xr[c]; s += v*v; }
    red[threadIdx.x] = s; __syncthreads();
    for (int o = 128; o > 0; o >>= 1) {
        if (threadIdx.x < o) red[threadIdx.x] += red[threadIdx.x+o];
        __syncthreads();
    }
    float inv = rsqrtf(red[0] * (1.f/DIN) + EPSF);
    for (int p = threadIdx.x; p < DIN/2; p += 256) {
        float2 v = ((const float2*)xr)[p];
        float2 ww = ((const float2*)w)[p];
        uint32_t hh, ll;
        split2(v.x*inv*ww.x, v.y*inv*ww.y, hh, ll);
        ((uint32_t*)oh)[(size_t)t*(DIN/2) + p] = hh;
        ((uint32_t*)ol)[(size_t)t*(DIN/2) + p] = ll;
    }
}

// ---------------- concat [sB;sC;sD0] -> split bf16 ----------------
__global__ void k_build_w128(const float* __restrict__ sB, const float* __restrict__ sC,
                             const float* __restrict__ sD0) {
    int i2 = blockIdx.x*blockDim.x + threadIdx.x;
    if (i2 >= NLAYER*128*DM/2) return;
    int i = i2*2;
    int l = i / (128*DM);
    int r = (i / DM) % 128;
    int k = i % DM;
    float v0, v1;
    if (r < 16)       { const float* p = &sB[((long)l*16 + r)*DM + k];      v0 = p[0]; v1 = p[1]; }
    else if (r < 32)  { const float* p = &sC[((long)l*16 + (r-16))*DM + k]; v0 = p[0]; v1 = p[1]; }
    else              { const float* p = &sD0[((long)l*96 + (r-32))*DM + k];v0 = p[0]; v1 = p[1]; }
    uint32_t hh, ll;
    split2(v0, v1, hh, ll);
    ((uint32_t*)g_w128h)[i2] = hh;
    ((uint32_t*)g_w128l)[i2] = ll;
}

// ---------------- depthwise causal conv (K=4) + silu -> fp32 + split ----------------
__global__ void k_conv_silu(const float* __restrict__ cw, const float* __restrict__ cb) {
    int i = blockIdx.x*blockDim.x + threadIdx.x;
    if (i >= T_TOK*DM) return;
    int t = i / DM, d = i % DM;
    int l = t % SEQLEN;
    float acc = cb[d];
    #pragma unroll
    for (int j = 0; j < KCONV; j++) {
        int lj = l - (KCONV-1) + j;
        if (lj >= 0) acc += cw[d*KCONV + j] * g_ab[(long)(t - (KCONV-1) + j)*(2*DM) + d];
    }
    float v = siluf(acc);
    g_a[i] = v;
    __nv_bfloat16 hh = __float2bfloat16_rn(v);
    g_ah[i] = hh;
    g_al[i] = __float2bfloat16_rn(v - __bfloat162float(hh));
}

// ---------------- SSM scan: block-cooperative, SMEM-staged, double-buffered --
#define SCH 16
__global__ void __launch_bounds__(128)
k_scan(const float* __restrict__ A_log, const float* __restrict__ Dp) {
    __shared__ float sdv[2][SCH][32];
    __shared__ float sav[2][SCH][32];
    __shared__ float sbc[2][SCH][32];   // cols 0-15 B, 16-31 C
    __shared__ float sbg[2][SCH][32];
    __shared__ float sy[SCH][32];

    int tid = threadIdx.x;
    int dq = tid >> 2;
    int sq = tid & 3;
    int b  = blockIdx.x / (DM/32);
    int d0 = (blockIdx.x % (DM/32)) * 32;
    int d  = d0 + dq;

    float Ads[4], h[4];
    #pragma unroll
    for (int j = 0; j < 4; j++) {
        Ads[j] = -__expf(A_log[d*DS + sq*4 + j]);
        h[j] = 0.f;
    }
    float Dd = Dp[d];

    int tt0[4], dd0[4];
    #pragma unroll
    for (int q = 0; q < 4; q++) { int idx = tid + 128*q; tt0[q] = idx >> 5; dd0[q] = idx & 31; }

    float rdv[4], rav[4], rbc[4], rbg[4];
    const size_t tb = (size_t)b * SEQLEN;

    #pragma unroll
    for (int q = 0; q < 4; q++) {
        size_t t = tb + tt0[q];
        rdv[q] = g_delta[t*DM + d0 + dd0[q]];
        rav[q] = g_a[t*DM + d0 + dd0[q]];
        rbc[q] = g_bcd[t*128 + dd0[q]];
        rbg[q] = g_ab[t*(2*DM) + DM + d0 + dd0[q]];
    }
    #pragma unroll
    for (int q = 0; q < 4; q++) {
        sdv[0][tt0[q]][dd0[q]] = rdv[q];
        sav[0][tt0[q]][dd0[q]] = rav[q];
        sbc[0][tt0[q]][dd0[q]] = rbc[q];
        sbg[0][tt0[q]][dd0[q]] = rbg[q];
    }
    __syncthreads();

    const int NCH = SEQLEN / SCH;
    for (int c = 0; c < NCH; c++) {
        int cur = c & 1;
        if (c + 1 < NCH) {
            #pragma unroll
            for (int q = 0; q < 4; q++) {
                size_t t = tb + (size_t)(c+1)*SCH + tt0[q];
                rdv[q] = g_delta[t*DM + d0 + dd0[q]];
                rav[q] = g_a[t*DM + d0 + dd0[q]];
                rbc[q] = g_bcd[t*128 + dd0[q]];
                rbg[q] = g_ab[t*(2*DM) + DM + d0 + dd0[q]];
            }
        }

        #pragma unroll
        for (int tt = 0; tt < SCH; tt++) {
            float dv = sdv[cur][tt][dq];
            float av = sav[cur][tt][dq];
            float dva = dv * av;
            float bm0 = sbc[cur][tt][sq*4+0], bm1 = sbc[cur][tt][sq*4+1];
            float bm2 = sbc[cur][tt][sq*4+2], bm3 = sbc[cur][tt][sq*4+3];
            float cm0 = sbc[cur][tt][16+sq*4+0], cm1 = sbc[cur][tt][16+sq*4+1];
            float cm2 = sbc[cur][tt][16+sq*4+2], cm3 = sbc[cur][tt][16+sq*4+3];
            h[0] = fmaf(__expf(dv*Ads[0]), h[0], dva*bm0);
            h[1] = fmaf(__expf(dv*Ads[1]), h[1], dva*bm1);
            h[2] = fmaf(__expf(dv*Ads[2]), h[2], dva*bm2);
            h[3] = fmaf(__expf(dv*Ads[3]), h[3], dva*bm3);
            float y = h[0]*cm0 + h[1]*cm1 + h[2]*cm2 + h[3]*cm3;
            y += __shfl_xor_sync(0xffffffffu, y, 1);
            y += __shfl_xor_sync(0xffffffffu, y, 2);
            if (sq == 0) {
                float bg = sbg[cur][tt][dq];
                sy[tt][dq] = (y + Dd*av) * siluf(bg);
            }
        }
        __syncthreads();

        #pragma unroll
        for (int q = 0; q < 4; q++) {
            size_t t = tb + (size_t)c*SCH + tt0[q];
            size_t idx = t*DM + d0 + dd0[q];
            float v = sy[tt0[q]][dd0[q]];
            __nv_bfloat16 hh = __float2bfloat16_rn(v);
            g_yh[idx] = hh;
            g_yl[idx] = __float2bfloat16_rn(v - __bfloat162float(hh));
        }

        if (c + 1 < NCH) {
            int nxt = cur ^ 1;
            #pragma unroll
            for (int q = 0; q < 4; q++) {
                sdv[nxt][tt0[q]][dd0[q]] = rdv[q];
                sav[nxt][tt0[q]][dd0[q]] = rav[q];
                sbc[nxt][tt0[q]][dd0[q]] = rbc[q];
                sbg[nxt][tt0[q]][dd0[q]] = rbg[q];
            }
            __syncthreads();
        }
    }
}

// ---------------- host launcher ----------------
extern "C" void kernel_launch(void* const* d_in, const int* in_sizes, int n_in,
                              void* d_out, int out_size) {
    const int*   tok      = (const int*)  d_in[0];
    const float* emb      = (const float*)d_in[1];
    const float* in_proj  = (const float*)d_in[2];
    const float* out_proj = (const float*)d_in[3];
    const float* sB       = (const float*)d_in[4];
    const float* sC       = (const float*)d_in[5];
    const float* sD0      = (const float*)d_in[6];
    const float* sD1w     = (const float*)d_in[7];
    const float* sD1b     = (const float*)d_in[8];
    const float* cw       = (const float*)d_in[9];
    const float* cb       = (const float*)d_in[10];
    const float* A_log    = (const float*)d_in[11];
    const float* Dp       = (const float*)d_in[12];
    const float* norm_w   = (const float*)d_in[13];
    const float* norm_f   = (const float*)d_in[14];
    const float* head_w   = (const float*)d_in[15];
    float* out = (float*)d_out;

    float *seq, *ab, *a, *bcd, *delta;
    __nv_bfloat16 *xnh, *xnl, *ah, *al, *dth, *dtl, *yh, *yl;
    __nv_bfloat16 *wih, *wil, *woh, *wol, *w128h, *w128l, *sd1h, *sd1l, *hwh, *hwl;
    cudaGetSymbolAddress((void**)&seq,   g_seq);
    cudaGetSymbolAddress((void**)&ab,    g_ab);
    cudaGetSymbolAddress((void**)&a,     g_a);
    cudaGetSymbolAddress((void**)&bcd,   g_bcd);
    cudaGetSymbolAddress((void**)&delta, g_delta);
    cudaGetSymbolAddress((void**)&xnh,   g_xnh);  cudaGetSymbolAddress((void**)&xnl, g_xnl);
    cudaGetSymbolAddress((void**)&ah,    g_ah);   cudaGetSymbolAddress((void**)&al,  g_al);
    cudaGetSymbolAddress((void**)&dth,   g_dth);  cudaGetSymbolAddress((void**)&dtl, g_dtl);
    cudaGetSymbolAddress((void**)&yh,    g_yh);   cudaGetSymbolAddress((void**)&yl,  g_yl);
    cudaGetSymbolAddress((void**)&wih,   g_wih);  cudaGetSymbolAddress((void**)&wil, g_wil);
    cudaGetSymbolAddress((void**)&woh,   g_woh);  cudaGetSymbolAddress((void**)&wol, g_wol);
    cudaGetSymbolAddress((void**)&w128h, g_w128h);cudaGetSymbolAddress((void**)&w128l, g_w128l);
    cudaGetSymbolAddress((void**)&sd1h,  g_sd1h); cudaGetSymbolAddress((void**)&sd1l, g_sd1l);
    cudaGetSymbolAddress((void**)&hwh,   g_hwh);  cudaGetSymbolAddress((void**)&hwl, g_hwl);

    static bool attr_done = false;
    if (!attr_done) {
        cudaFuncSetAttribute(k_gemm<0>, cudaFuncAttributeMaxDynamicSharedMemorySize, SMEM_G);
        cudaFuncSetAttribute(k_gemm<1>, cudaFuncAttributeMaxDynamicSharedMemorySize, SMEM_G);
        cudaFuncSetAttribute(k_gemm<2>, cudaFuncAttributeMaxDynamicSharedMemorySize, SMEM_G);
        cudaFuncSetAttribute(k_gemm<3>, cudaFuncAttributeMaxDynamicSharedMemorySize, SMEM_G);
        attr_done = true;
    }

    // weight pre-split (deterministic every call; graph-capturable)
    k_split<<<(NLAYER*2*DM*DIN/2 + 255)/256, 256>>>(in_proj,  wih, wil, NLAYER*2*DM*DIN/2);
    k_split<<<(NLAYER*DIN*DM/2 + 255)/256, 256>>>(out_proj, woh, wol, NLAYER*DIN*DM/2);
    k_split<<<(NLAYER*DM*DD/2 + 255)/256, 256>>>(sD1w,     sd1h, sd1l, NLAYER*DM*DD/2);
    k_split<<<(VOCAB*DIN/2 + 255)/256, 256>>>(head_w,   hwh,  hwl,  VOCAB*DIN/2);
    k_build_w128<<<(NLAYER*128*DM/2 + 255)/256, 256>>>(sB, sC, sD0);
    k_embed<<<(T_TOK*DIN + 255)/256, 256>>>(tok, emb);

    for (int i = 0; i < NLAYER; i++) {
        k_rmsnorm<<<T_TOK, 256>>>(seq, norm_w + (long)i*DIN, xnh, xnl);
        // ab = x @ in_proj^T   [T, 3072]
        {
            dim3 g(2*DM/128, T_TOK/128);
            k_gemm<0><<<g, 256, SMEM_G>>>(xnh, xnl, wih + (long)i*2*DM*DIN, wil + (long)i*2*DM*DIN,
                                          ab, nullptr, nullptr, nullptr, DIN, 2*DM);
        }
        k_conv_silu<<<(T_TOK*DM + 255)/256, 256>>>(cw + (long)i*DM*KCONV, cb + (long)i*DM);
        // [Bm | Cm | dt(split)] = a @ w128^T   [T, 128]
        {
            dim3 g(1, T_TOK/128);
            k_gemm<3><<<g, 256, SMEM_G>>>(ah, al, w128h + (long)i*128*DM, w128l + (long)i*128*DM,
                                          bcd, nullptr, dth, dtl, DM, 128);
        }
        // delta = softplus(dt @ sD1^T + b)   [T, 1536]
        {
            dim3 g(DM/128, T_TOK/128);
            k_gemm<2><<<g, 256, SMEM_G>>>(dth, dtl, sd1h + (long)i*DM*DD, sd1l + (long)i*DM*DD,
                                          delta, sD1b + (long)i*DM, nullptr, nullptr, DD, DM);
        }
        k_scan<<<BATCH*(DM/32), 128>>>(A_log + (long)i*DM*DS, Dp + (long)i*DM);
        // seq += y @ out_proj^T
        {
            dim3 g(DIN/128, T_TOK/128);
            k_gemm<1><<<g, 256, SMEM_G>>>(yh, yl, woh + (long)i*DIN*DM, wol + (long)i*DIN*DM,
                                          seq, nullptr, nullptr, nullptr, DM, DIN);
        }
    }

    k_rmsnorm<<<T_TOK, 256>>>(seq, norm_f, xnh, xnl);
    {
        dim3 g(VOCAB/128, T_TOK/128);
        k_gemm<0><<<g, 256, SMEM_G>>>(xnh, xnl, hwh, hwl, out, nullptr, nullptr, nullptr,
                                      DIN, VOCAB);
    }
}